// round 3
// baseline (speedup 1.0000x reference)
#include <cuda_runtime.h>
#include <cuda_bf16.h>
#include <cstddef>

// Problem constants
#define BATCH 2
#define SEQ   2048
#define EMB   1024
#define NH    16
#define HD    64
#define INNER (NH * HD)   // 1024
#define MTOT  (BATCH * SEQ) // 4096

// Scratch buffers (allocation-free rule: __device__ globals)
__device__ float g_q[BATCH * NH * SEQ * HD];
__device__ float g_k[BATCH * NH * SEQ * HD];
__device__ float g_v[BATCH * NH * SEQ * HD];
__device__ float g_ctx[BATCH * SEQ * INNER];

// ---------------------------------------------------------------------------
// NT GEMM: C[m,n] = sum_k X[m,k] * W[n,k]   (X row-major MxK, W row-major NxK)
// Tiles: BM=BN=64, BK=16, 256 threads, 4x4 microtile per thread.
// mode 0: out[m*N+n] = acc + bias[n]
// mode 1: scatter to (b,h,s,d) layout: out[((b*NH+h)*SEQ+s)*HD + d]
// ---------------------------------------------------------------------------
__global__ void __launch_bounds__(256) gemm_nt_kernel(
    const float* __restrict__ X, const float* __restrict__ W,
    float* __restrict__ out, const float* __restrict__ bias,
    int M, int N, int K, int mode)
{
    __shared__ float Xs[16][68];
    __shared__ float Ws[16][68];

    const int tid = threadIdx.x;
    const int tx = tid & 15;
    const int ty = tid >> 4;
    const int row0 = blockIdx.y * 64;
    const int col0 = blockIdx.x * 64;
    const int lrow = tid >> 2;        // 0..63
    const int lk4  = (tid & 3) << 2;  // 0,4,8,12

    float acc[4][4] = {};

    for (int k0 = 0; k0 < K; k0 += 16) {
        float4 xv = *(const float4*)&X[(size_t)(row0 + lrow) * K + k0 + lk4];
        float4 wv = *(const float4*)&W[(size_t)(col0 + lrow) * K + k0 + lk4];
        Xs[lk4 + 0][lrow] = xv.x;
        Xs[lk4 + 1][lrow] = xv.y;
        Xs[lk4 + 2][lrow] = xv.z;
        Xs[lk4 + 3][lrow] = xv.w;
        Ws[lk4 + 0][lrow] = wv.x;
        Ws[lk4 + 1][lrow] = wv.y;
        Ws[lk4 + 2][lrow] = wv.z;
        Ws[lk4 + 3][lrow] = wv.w;
        __syncthreads();

        #pragma unroll
        for (int kk = 0; kk < 16; kk++) {
            float4 a = *(const float4*)&Xs[kk][ty * 4];
            float4 b = *(const float4*)&Ws[kk][tx * 4];
            float av[4] = {a.x, a.y, a.z, a.w};
            float bv[4] = {b.x, b.y, b.z, b.w};
            #pragma unroll
            for (int i = 0; i < 4; i++)
                #pragma unroll
                for (int j = 0; j < 4; j++)
                    acc[i][j] += av[i] * bv[j];
        }
        __syncthreads();
    }

    #pragma unroll
    for (int i = 0; i < 4; i++) {
        int m = row0 + ty * 4 + i;
        #pragma unroll
        for (int j = 0; j < 4; j++) {
            int n = col0 + tx * 4 + j;
            float v = acc[i][j];
            if (bias) v += bias[n];
            if (mode == 0) {
                out[(size_t)m * N + n] = v;
            } else {
                int b = m >> 11;      // m / SEQ
                int s = m & 2047;     // m % SEQ
                int h = n >> 6;       // n / HD
                int d = n & 63;       // n % HD
                out[(((size_t)(b * NH + h)) * SEQ + s) * HD + d] = v;
            }
        }
    }
}

// ---------------------------------------------------------------------------
// Flash attention: one block per (q-tile of 64 rows, b*h).
// smem layouts (stride SDIM=68 to dodge conflicts):
//   Qs[d][row], Ks[d][col]  (d-major so the QK^T inner loop uses float4 LDS)
//   Vs[col][d], Ps[col][row] (col-major so the PV inner loop uses float4 LDS)
// positional_mask arrives as int32 (harness converts bool -> int32).
// ---------------------------------------------------------------------------
#define SDIM 68
__global__ void __launch_bounds__(256) flash_kernel(
    const int* __restrict__ pmask,            // (B, SEQ) int32 (bool)
    const int* __restrict__ fmask,            // scalar int32
    float* __restrict__ ctx)                  // (B, SEQ, INNER)
{
    extern __shared__ float sm[];
    float* Qs   = sm;                 // 64*SDIM
    float* Ks   = Qs + 64 * SDIM;
    float* Vs   = Ks + 64 * SDIM;
    float* Ps   = Vs + 64 * SDIM;
    float* rowm = Ps + 64 * SDIM;     // 64
    float* rowl = rowm + 64;          // 64
    float* rowc = rowl + 64;          // 64
    float* red  = rowc + 64;          // 64*16

    const int tid = threadIdx.x;
    const int tx = tid & 15;
    const int ty = tid >> 4;
    const int qt = blockIdx.x;        // q tile index, 0..31
    const int bh = blockIdx.y;        // 0..31
    const int b  = bh >> 4;
    const int h  = bh & 15;

    const float* Qg = g_q + (size_t)bh * SEQ * HD;
    const float* Kg = g_k + (size_t)bh * SEQ * HD;
    const float* Vg = g_v + (size_t)bh * SEQ * HD;
    const int fut = fmask[0];

    // Load Q tile transposed, pre-scaled by 1/sqrt(HD)
    for (int e = tid; e < 64 * 16; e += 256) {
        int r  = e >> 4;
        int c4 = (e & 15) << 2;
        float4 v = *(const float4*)&Qg[(size_t)(qt * 64 + r) * HD + c4];
        Qs[(c4 + 0) * SDIM + r] = v.x * 0.125f;
        Qs[(c4 + 1) * SDIM + r] = v.y * 0.125f;
        Qs[(c4 + 2) * SDIM + r] = v.z * 0.125f;
        Qs[(c4 + 3) * SDIM + r] = v.w * 0.125f;
    }
    if (tid < 64) { rowm[tid] = -1e30f; rowl[tid] = 0.0f; }

    float acc[4][4] = {};   // O microtile: [row i][d j]

    const int ktmax = fut ? qt : (SEQ / 64 - 1);
    for (int kt = 0; kt <= ktmax; kt++) {
        __syncthreads();  // previous iteration's reads of Ks/Vs/Ps complete

        // Load K tile (transposed) and V tile (natural)
        for (int e = tid; e < 64 * 16; e += 256) {
            int r  = e >> 4;
            int c4 = (e & 15) << 2;
            float4 kv = *(const float4*)&Kg[(size_t)(kt * 64 + r) * HD + c4];
            Ks[(c4 + 0) * SDIM + r] = kv.x;
            Ks[(c4 + 1) * SDIM + r] = kv.y;
            Ks[(c4 + 2) * SDIM + r] = kv.z;
            Ks[(c4 + 3) * SDIM + r] = kv.w;
            float4 vv = *(const float4*)&Vg[(size_t)(kt * 64 + r) * HD + c4];
            *(float4*)&Vs[r * SDIM + c4] = vv;
        }
        __syncthreads();

        // S = (Q * scale) K^T for this thread's 4x4
        float s[4][4] = {};
        #pragma unroll 8
        for (int d = 0; d < 64; d++) {
            float4 qa = *(const float4*)&Qs[d * SDIM + ty * 4];
            float4 ka = *(const float4*)&Ks[d * SDIM + tx * 4];
            float av[4] = {qa.x, qa.y, qa.z, qa.w};
            float bv[4] = {ka.x, ka.y, ka.z, ka.w};
            #pragma unroll
            for (int i = 0; i < 4; i++)
                #pragma unroll
                for (int j = 0; j < 4; j++)
                    s[i][j] += av[i] * bv[j];
        }

        // Masks + per-thread row max
        #pragma unroll
        for (int i = 0; i < 4; i++) {
            int r = qt * 64 + ty * 4 + i;
            float pmax = -1e30f;
            #pragma unroll
            for (int j = 0; j < 4; j++) {
                int c = kt * 64 + tx * 4 + j;
                float sv = s[i][j];
                if (pmask[b * SEQ + c] == 0) sv = -1e30f;
                if (fut && c > r) sv = -1e30f;
                s[i][j] = sv;
                pmax = fmaxf(pmax, sv);
            }
            red[(ty * 4 + i) * 16 + tx] = pmax;
        }
        __syncthreads();

        // Row max reduce + correction factor
        if (tid < 64) {
            float mt = red[tid * 16];
            #pragma unroll
            for (int t = 1; t < 16; t++) mt = fmaxf(mt, red[tid * 16 + t]);
            float mold = rowm[tid];
            float mnew = fmaxf(mold, mt);
            rowc[tid] = __expf(mold - mnew);
            rowm[tid] = mnew;
        }
        __syncthreads();

        // P = exp(S - m), row sums, rescale O, stash P transposed
        #pragma unroll
        for (int i = 0; i < 4; i++) {
            int ri = ty * 4 + i;
            float ci = rowc[ri];
            float mi = rowm[ri];
            float psum = 0.0f;
            #pragma unroll
            for (int j = 0; j < 4; j++) {
                float p = __expf(s[i][j] - mi);
                psum += p;
                Ps[(tx * 4 + j) * SDIM + ri] = p;
                acc[i][j] *= ci;
            }
            red[ri * 16 + tx] = psum;
        }
        __syncthreads();

        if (tid < 64) {
            float ssum = 0.0f;
            #pragma unroll
            for (int t = 0; t < 16; t++) ssum += red[tid * 16 + t];
            rowl[tid] = rowl[tid] * rowc[tid] + ssum;
        }

        // O += P @ V
        #pragma unroll 8
        for (int c = 0; c < 64; c++) {
            float4 pa = *(const float4*)&Ps[c * SDIM + ty * 4];
            float4 va = *(const float4*)&Vs[c * SDIM + tx * 4];
            float pv[4] = {pa.x, pa.y, pa.z, pa.w};
            float vv[4] = {va.x, va.y, va.z, va.w};
            #pragma unroll
            for (int i = 0; i < 4; i++)
                #pragma unroll
                for (int j = 0; j < 4; j++)
                    acc[i][j] += pv[i] * vv[j];
        }
    }
    __syncthreads();  // rowl final

    #pragma unroll
    for (int i = 0; i < 4; i++) {
        int r = qt * 64 + ty * 4 + i;
        float l = rowl[ty * 4 + i];
        float inv = (l > 0.0f) ? (1.0f / l) : 0.0f;
        #pragma unroll
        for (int j = 0; j < 4; j++) {
            ctx[((size_t)b * SEQ + r) * INNER + h * HD + tx * 4 + j] =
                acc[i][j] * inv;
        }
    }
}

// ---------------------------------------------------------------------------
// Launch
// ---------------------------------------------------------------------------
extern "C" void kernel_launch(void* const* d_in, const int* in_sizes, int n_in,
                              void* d_out, int out_size)
{
    const float* q  = (const float*)d_in[0];
    const float* k  = (const float*)d_in[1];
    const float* v  = (const float*)d_in[2];
    const int*   pm = (const int*)d_in[3];
    const int*   fm = (const int*)d_in[4];
    const float* Wq = (const float*)d_in[5];
    const float* Wk = (const float*)d_in[6];
    const float* Wv = (const float*)d_in[7];
    const float* Wo = (const float*)d_in[8];
    const float* bo = (const float*)d_in[9];
    float* out = (float*)d_out;

    float *gq, *gk, *gv, *gctx;
    cudaGetSymbolAddress((void**)&gq,   g_q);
    cudaGetSymbolAddress((void**)&gk,   g_k);
    cudaGetSymbolAddress((void**)&gv,   g_v);
    cudaGetSymbolAddress((void**)&gctx, g_ctx);

    dim3 gblk(256);
    dim3 ggrd(INNER / 64, MTOT / 64);  // (16, 64)

    // QKV projections -> (B,H,S,D) layout
    gemm_nt_kernel<<<ggrd, gblk>>>(q, Wq, gq, nullptr, MTOT, INNER, EMB, 1);
    gemm_nt_kernel<<<ggrd, gblk>>>(k, Wk, gk, nullptr, MTOT, INNER, EMB, 1);
    gemm_nt_kernel<<<ggrd, gblk>>>(v, Wv, gv, nullptr, MTOT, INNER, EMB, 1);

    // Flash attention
    int smem = (4 * 64 * SDIM + 3 * 64 + 64 * 16) * (int)sizeof(float);
    cudaFuncSetAttribute(flash_kernel,
                         cudaFuncAttributeMaxDynamicSharedMemorySize, smem);
    flash_kernel<<<dim3(SEQ / 64, BATCH * NH), 256, smem>>>(pm, fm, gctx);

    // Output projection + bias
    gemm_nt_kernel<<<ggrd, gblk>>>(gctx, Wo, out, bo, MTOT, EMB, INNER, 0);
}

// round 4
// speedup vs baseline: 1.6816x; 1.6816x over previous
#include <cuda_runtime.h>
#include <cuda_bf16.h>
#include <cstddef>

// Problem constants
#define BATCH 2
#define SEQ   2048
#define EMB   1024
#define NH    16
#define HD    64
#define INNER (NH * HD)     // 1024
#define MTOT  (BATCH * SEQ) // 4096

// Scratch buffers (allocation-free rule: __device__ globals)
__device__ float g_q[BATCH * NH * SEQ * HD];
__device__ float g_k[BATCH * NH * SEQ * HD];
__device__ float g_v[BATCH * NH * SEQ * HD];
__device__ float g_ctx[BATCH * SEQ * INNER];

// ---------------------------------------------------------------------------
// tf32 helpers
// ---------------------------------------------------------------------------
__device__ __forceinline__ unsigned f2tf32(float f) {
    unsigned u;
    asm("cvt.rna.tf32.f32 %0, %1;" : "=r"(u) : "f"(f));
    return u;
}

__device__ __forceinline__ void mma_tf32(
    float& c0, float& c1, float& c2, float& c3,
    unsigned a0, unsigned a1, unsigned a2, unsigned a3,
    unsigned b0, unsigned b1)
{
    asm volatile(
        "mma.sync.aligned.m16n8k8.row.col.f32.tf32.tf32.f32 "
        "{%0,%1,%2,%3}, {%4,%5,%6,%7}, {%8,%9}, {%0,%1,%2,%3};"
        : "+f"(c0), "+f"(c1), "+f"(c2), "+f"(c3)
        : "r"(a0), "r"(a1), "r"(a2), "r"(a3), "r"(b0), "r"(b1));
}

// ---------------------------------------------------------------------------
// tf32 tensor-core NT GEMM: C[m,n] = sum_k X[m,k] * W[n,k]
// Block tile 128x128, BK=32, 256 threads (8 warps), warp tile 64x32.
// Warp grid: 2 (m) x 4 (n). Each warp: 4x4 grid of m16n8k8 mma.
// Smem stride 36 words -> conflict-free fragment loads ((4g+tig)%32 distinct).
// mode 0: out[m*N+n] = acc (+ bias[n])
// mode 1: scatter to (b,h,s,d): out[((b*NH+h)*SEQ+s)*HD + d]
// ---------------------------------------------------------------------------
#define GS 36
__global__ void __launch_bounds__(256) gemm_tc_kernel(
    const float* __restrict__ X, const float* __restrict__ W,
    float* __restrict__ out, const float* __restrict__ bias,
    int M, int N, int K, int mode)
{
    __shared__ unsigned As[128 * GS];
    __shared__ unsigned Bs[128 * GS];

    const int tid  = threadIdx.x;
    const int warp = tid >> 5;
    const int lane = tid & 31;
    const int g    = lane >> 2;   // groupID
    const int tig  = lane & 3;    // thread in group

    const int row0 = blockIdx.y * 128;
    const int col0 = blockIdx.x * 128;
    const int wm   = (warp >> 2) * 64;  // warp m offset: 0 or 64
    const int wn   = (warp & 3) * 32;   // warp n offset: 0,32,64,96

    // gmem staging: 4 float4 per operand per tile
    const int srow = tid >> 3;          // 0..31 (row step 32)
    const int sc4  = (tid & 7) << 2;    // 0,4,...,28

    float acc[4][4][4] = {};            // [mi][ni][c0..c3]
    float4 xv[4], wv[4];

    const int ktiles = K >> 5;

    // Prologue: load tile 0
    #pragma unroll
    for (int i = 0; i < 4; i++) {
        int r = srow + i * 32;
        xv[i] = *(const float4*)&X[(size_t)(row0 + r) * K + sc4];
        wv[i] = *(const float4*)&W[(size_t)(col0 + r) * K + sc4];
    }

    for (int t = 0; t < ktiles; t++) {
        // store staged tile to smem (with tf32 convert)
        #pragma unroll
        for (int i = 0; i < 4; i++) {
            int r = srow + i * 32;
            unsigned* pa = &As[r * GS + sc4];
            pa[0] = f2tf32(xv[i].x); pa[1] = f2tf32(xv[i].y);
            pa[2] = f2tf32(xv[i].z); pa[3] = f2tf32(xv[i].w);
            unsigned* pb = &Bs[r * GS + sc4];
            pb[0] = f2tf32(wv[i].x); pb[1] = f2tf32(wv[i].y);
            pb[2] = f2tf32(wv[i].z); pb[3] = f2tf32(wv[i].w);
        }
        __syncthreads();

        // prefetch next tile into registers
        if (t + 1 < ktiles) {
            int k0 = (t + 1) << 5;
            #pragma unroll
            for (int i = 0; i < 4; i++) {
                int r = srow + i * 32;
                xv[i] = *(const float4*)&X[(size_t)(row0 + r) * K + k0 + sc4];
                wv[i] = *(const float4*)&W[(size_t)(col0 + r) * K + k0 + sc4];
            }
        }

        // 4 k8-steps of mma from smem
        #pragma unroll
        for (int kk = 0; kk < 4; kk++) {
            int k0 = kk << 3;
            unsigned a[4][4], b[4][2];
            #pragma unroll
            for (int mi = 0; mi < 4; mi++) {
                int rb = wm + mi * 16;
                a[mi][0] = As[(rb + g)     * GS + k0 + tig];
                a[mi][1] = As[(rb + g + 8) * GS + k0 + tig];
                a[mi][2] = As[(rb + g)     * GS + k0 + tig + 4];
                a[mi][3] = As[(rb + g + 8) * GS + k0 + tig + 4];
            }
            #pragma unroll
            for (int ni = 0; ni < 4; ni++) {
                int cb = wn + ni * 8;
                b[ni][0] = Bs[(cb + g) * GS + k0 + tig];
                b[ni][1] = Bs[(cb + g) * GS + k0 + tig + 4];
            }
            #pragma unroll
            for (int mi = 0; mi < 4; mi++)
                #pragma unroll
                for (int ni = 0; ni < 4; ni++)
                    mma_tf32(acc[mi][ni][0], acc[mi][ni][1],
                             acc[mi][ni][2], acc[mi][ni][3],
                             a[mi][0], a[mi][1], a[mi][2], a[mi][3],
                             b[ni][0], b[ni][1]);
        }
        __syncthreads();
    }

    // Epilogue: c0/c1 at (row g, cols 2*tig, 2*tig+1), c2/c3 at row g+8
    #pragma unroll
    for (int mi = 0; mi < 4; mi++) {
        #pragma unroll
        for (int half = 0; half < 2; half++) {
            int m = row0 + wm + mi * 16 + g + half * 8;
            #pragma unroll
            for (int ni = 0; ni < 4; ni++) {
                int n = col0 + wn + ni * 8 + tig * 2;
                float v0 = acc[mi][ni][half * 2 + 0];
                float v1 = acc[mi][ni][half * 2 + 1];
                if (bias) { v0 += bias[n]; v1 += bias[n + 1]; }
                if (mode == 0) {
                    out[(size_t)m * N + n]     = v0;
                    out[(size_t)m * N + n + 1] = v1;
                } else {
                    int b_  = m >> 11;
                    int s_  = m & 2047;
                    int h_  = n >> 6;
                    int d_  = n & 63;
                    size_t base = (((size_t)(b_ * NH + h_)) * SEQ + s_) * HD;
                    out[base + d_]     = v0;
                    out[base + d_ + 1] = v1;
                }
            }
        }
    }
}

// ---------------------------------------------------------------------------
// Flash attention: one block per (q-tile of 64 rows, b*h). (unchanged)
// ---------------------------------------------------------------------------
#define SDIM 68
__global__ void __launch_bounds__(256) flash_kernel(
    const int* __restrict__ pmask,            // (B, SEQ) int32 (bool)
    const int* __restrict__ fmask,            // scalar int32
    float* __restrict__ ctx)                  // (B, SEQ, INNER)
{
    extern __shared__ float sm[];
    float* Qs   = sm;                 // 64*SDIM
    float* Ks   = Qs + 64 * SDIM;
    float* Vs   = Ks + 64 * SDIM;
    float* Ps   = Vs + 64 * SDIM;
    float* rowm = Ps + 64 * SDIM;     // 64
    float* rowl = rowm + 64;          // 64
    float* rowc = rowl + 64;          // 64
    float* red  = rowc + 64;          // 64*16

    const int tid = threadIdx.x;
    const int tx = tid & 15;
    const int ty = tid >> 4;
    const int qt = blockIdx.x;        // q tile index, 0..31
    const int bh = blockIdx.y;        // 0..31
    const int b  = bh >> 4;
    const int h  = bh & 15;

    const float* Qg = g_q + (size_t)bh * SEQ * HD;
    const float* Kg = g_k + (size_t)bh * SEQ * HD;
    const float* Vg = g_v + (size_t)bh * SEQ * HD;
    const int fut = fmask[0];

    // Load Q tile transposed, pre-scaled by 1/sqrt(HD)
    for (int e = tid; e < 64 * 16; e += 256) {
        int r  = e >> 4;
        int c4 = (e & 15) << 2;
        float4 v = *(const float4*)&Qg[(size_t)(qt * 64 + r) * HD + c4];
        Qs[(c4 + 0) * SDIM + r] = v.x * 0.125f;
        Qs[(c4 + 1) * SDIM + r] = v.y * 0.125f;
        Qs[(c4 + 2) * SDIM + r] = v.z * 0.125f;
        Qs[(c4 + 3) * SDIM + r] = v.w * 0.125f;
    }
    if (tid < 64) { rowm[tid] = -1e30f; rowl[tid] = 0.0f; }

    float acc[4][4] = {};   // O microtile: [row i][d j]

    const int ktmax = fut ? qt : (SEQ / 64 - 1);
    for (int kt = 0; kt <= ktmax; kt++) {
        __syncthreads();  // previous iteration's reads of Ks/Vs/Ps complete

        // Load K tile (transposed) and V tile (natural)
        for (int e = tid; e < 64 * 16; e += 256) {
            int r  = e >> 4;
            int c4 = (e & 15) << 2;
            float4 kv = *(const float4*)&Kg[(size_t)(kt * 64 + r) * HD + c4];
            Ks[(c4 + 0) * SDIM + r] = kv.x;
            Ks[(c4 + 1) * SDIM + r] = kv.y;
            Ks[(c4 + 2) * SDIM + r] = kv.z;
            Ks[(c4 + 3) * SDIM + r] = kv.w;
            float4 vv = *(const float4*)&Vg[(size_t)(kt * 64 + r) * HD + c4];
            *(float4*)&Vs[r * SDIM + c4] = vv;
        }
        __syncthreads();

        // S = (Q * scale) K^T for this thread's 4x4
        float s[4][4] = {};
        #pragma unroll 8
        for (int d = 0; d < 64; d++) {
            float4 qa = *(const float4*)&Qs[d * SDIM + ty * 4];
            float4 ka = *(const float4*)&Ks[d * SDIM + tx * 4];
            float av[4] = {qa.x, qa.y, qa.z, qa.w};
            float bv[4] = {ka.x, ka.y, ka.z, ka.w};
            #pragma unroll
            for (int i = 0; i < 4; i++)
                #pragma unroll
                for (int j = 0; j < 4; j++)
                    s[i][j] += av[i] * bv[j];
        }

        // Masks + per-thread row max
        #pragma unroll
        for (int i = 0; i < 4; i++) {
            int r = qt * 64 + ty * 4 + i;
            float pmax = -1e30f;
            #pragma unroll
            for (int j = 0; j < 4; j++) {
                int c = kt * 64 + tx * 4 + j;
                float sv = s[i][j];
                if (pmask[b * SEQ + c] == 0) sv = -1e30f;
                if (fut && c > r) sv = -1e30f;
                s[i][j] = sv;
                pmax = fmaxf(pmax, sv);
            }
            red[(ty * 4 + i) * 16 + tx] = pmax;
        }
        __syncthreads();

        // Row max reduce + correction factor
        if (tid < 64) {
            float mt = red[tid * 16];
            #pragma unroll
            for (int t = 1; t < 16; t++) mt = fmaxf(mt, red[tid * 16 + t]);
            float mold = rowm[tid];
            float mnew = fmaxf(mold, mt);
            rowc[tid] = __expf(mold - mnew);
            rowm[tid] = mnew;
        }
        __syncthreads();

        // P = exp(S - m), row sums, rescale O, stash P transposed
        #pragma unroll
        for (int i = 0; i < 4; i++) {
            int ri = ty * 4 + i;
            float ci = rowc[ri];
            float mi = rowm[ri];
            float psum = 0.0f;
            #pragma unroll
            for (int j = 0; j < 4; j++) {
                float p = __expf(s[i][j] - mi);
                psum += p;
                Ps[(tx * 4 + j) * SDIM + ri] = p;
                acc[i][j] *= ci;
            }
            red[ri * 16 + tx] = psum;
        }
        __syncthreads();

        if (tid < 64) {
            float ssum = 0.0f;
            #pragma unroll
            for (int t = 0; t < 16; t++) ssum += red[tid * 16 + t];
            rowl[tid] = rowl[tid] * rowc[tid] + ssum;
        }

        // O += P @ V
        #pragma unroll 8
        for (int c = 0; c < 64; c++) {
            float4 pa = *(const float4*)&Ps[c * SDIM + ty * 4];
            float4 va = *(const float4*)&Vs[c * SDIM + tx * 4];
            float pv[4] = {pa.x, pa.y, pa.z, pa.w};
            float vv[4] = {va.x, va.y, va.z, va.w};
            #pragma unroll
            for (int i = 0; i < 4; i++)
                #pragma unroll
                for (int j = 0; j < 4; j++)
                    acc[i][j] += pv[i] * vv[j];
        }
    }
    __syncthreads();  // rowl final

    #pragma unroll
    for (int i = 0; i < 4; i++) {
        int r = qt * 64 + ty * 4 + i;
        float l = rowl[ty * 4 + i];
        float inv = (l > 0.0f) ? (1.0f / l) : 0.0f;
        #pragma unroll
        for (int j = 0; j < 4; j++) {
            ctx[((size_t)b * SEQ + r) * INNER + h * HD + tx * 4 + j] =
                acc[i][j] * inv;
        }
    }
}

// ---------------------------------------------------------------------------
// Launch
// ---------------------------------------------------------------------------
extern "C" void kernel_launch(void* const* d_in, const int* in_sizes, int n_in,
                              void* d_out, int out_size)
{
    const float* q  = (const float*)d_in[0];
    const float* k  = (const float*)d_in[1];
    const float* v  = (const float*)d_in[2];
    const int*   pm = (const int*)d_in[3];
    const int*   fm = (const int*)d_in[4];
    const float* Wq = (const float*)d_in[5];
    const float* Wk = (const float*)d_in[6];
    const float* Wv = (const float*)d_in[7];
    const float* Wo = (const float*)d_in[8];
    const float* bo = (const float*)d_in[9];
    float* out = (float*)d_out;

    float *gq, *gk, *gv, *gctx;
    cudaGetSymbolAddress((void**)&gq,   g_q);
    cudaGetSymbolAddress((void**)&gk,   g_k);
    cudaGetSymbolAddress((void**)&gv,   g_v);
    cudaGetSymbolAddress((void**)&gctx, g_ctx);

    dim3 gblk(256);
    dim3 ggrd(INNER / 128, MTOT / 128);  // (8, 32)

    // QKV projections -> (B,H,S,D) layout (tf32 tensor cores)
    gemm_tc_kernel<<<ggrd, gblk>>>(q, Wq, gq, nullptr, MTOT, INNER, EMB, 1);
    gemm_tc_kernel<<<ggrd, gblk>>>(k, Wk, gk, nullptr, MTOT, INNER, EMB, 1);
    gemm_tc_kernel<<<ggrd, gblk>>>(v, Wv, gv, nullptr, MTOT, INNER, EMB, 1);

    // Flash attention (fp32 SIMT)
    int smem = (4 * 64 * SDIM + 3 * 64 + 64 * 16) * (int)sizeof(float);
    cudaFuncSetAttribute(flash_kernel,
                         cudaFuncAttributeMaxDynamicSharedMemorySize, smem);
    flash_kernel<<<dim3(SEQ / 64, BATCH * NH), 256, smem>>>(pm, fm, gctx);

    // Output projection + bias (tf32 tensor cores)
    gemm_tc_kernel<<<ggrd, gblk>>>(gctx, Wo, out, bo, MTOT, EMB, INNER, 0);
}

// round 5
// speedup vs baseline: 3.5199x; 2.0932x over previous
#include <cuda_runtime.h>
#include <cuda_bf16.h>
#include <cstddef>

// Problem constants
#define BATCH 2
#define SEQ   2048
#define EMB   1024
#define NH    16
#define HD    64
#define INNER (NH * HD)     // 1024
#define MTOT  (BATCH * SEQ) // 4096

// Scratch buffers (allocation-free rule: __device__ globals)
__device__ float g_q[BATCH * NH * SEQ * HD];
__device__ float g_k[BATCH * NH * SEQ * HD];
__device__ float g_v[BATCH * NH * SEQ * HD];
__device__ float g_ctx[BATCH * SEQ * INNER];

// ---------------------------------------------------------------------------
// tf32 helpers
// ---------------------------------------------------------------------------
__device__ __forceinline__ unsigned f2tf32(float f) {
    unsigned u;
    asm("cvt.rna.tf32.f32 %0, %1;" : "=r"(u) : "f"(f));
    return u;
}

__device__ __forceinline__ void mma_tf32(
    float& c0, float& c1, float& c2, float& c3,
    unsigned a0, unsigned a1, unsigned a2, unsigned a3,
    unsigned b0, unsigned b1)
{
    asm volatile(
        "mma.sync.aligned.m16n8k8.row.col.f32.tf32.tf32.f32 "
        "{%0,%1,%2,%3}, {%4,%5,%6,%7}, {%8,%9}, {%0,%1,%2,%3};"
        : "+f"(c0), "+f"(c1), "+f"(c2), "+f"(c3)
        : "r"(a0), "r"(a1), "r"(a2), "r"(a3), "r"(b0), "r"(b1));
}

__device__ __forceinline__ void cp16(void* smem, const void* gmem) {
    unsigned a = (unsigned)__cvta_generic_to_shared(smem);
    asm volatile("cp.async.cg.shared.global [%0], [%1], 16;"
                 :: "r"(a), "l"(gmem));
}

// ---------------------------------------------------------------------------
// tf32 tensor-core NT GEMM (unchanged from R4): C[m,n] = sum_k X[m,k]*W[n,k]
// ---------------------------------------------------------------------------
#define GS 36
__global__ void __launch_bounds__(256) gemm_tc_kernel(
    const float* __restrict__ X, const float* __restrict__ W,
    float* __restrict__ out, const float* __restrict__ bias,
    int M, int N, int K, int mode)
{
    __shared__ unsigned As[128 * GS];
    __shared__ unsigned Bs[128 * GS];

    const int tid  = threadIdx.x;
    const int warp = tid >> 5;
    const int lane = tid & 31;
    const int g    = lane >> 2;
    const int tig  = lane & 3;

    const int row0 = blockIdx.y * 128;
    const int col0 = blockIdx.x * 128;
    const int wm   = (warp >> 2) * 64;
    const int wn   = (warp & 3) * 32;

    const int srow = tid >> 3;
    const int sc4  = (tid & 7) << 2;

    float acc[4][4][4] = {};
    float4 xv[4], wv[4];

    const int ktiles = K >> 5;

    #pragma unroll
    for (int i = 0; i < 4; i++) {
        int r = srow + i * 32;
        xv[i] = *(const float4*)&X[(size_t)(row0 + r) * K + sc4];
        wv[i] = *(const float4*)&W[(size_t)(col0 + r) * K + sc4];
    }

    for (int t = 0; t < ktiles; t++) {
        #pragma unroll
        for (int i = 0; i < 4; i++) {
            int r = srow + i * 32;
            unsigned* pa = &As[r * GS + sc4];
            pa[0] = f2tf32(xv[i].x); pa[1] = f2tf32(xv[i].y);
            pa[2] = f2tf32(xv[i].z); pa[3] = f2tf32(xv[i].w);
            unsigned* pb = &Bs[r * GS + sc4];
            pb[0] = f2tf32(wv[i].x); pb[1] = f2tf32(wv[i].y);
            pb[2] = f2tf32(wv[i].z); pb[3] = f2tf32(wv[i].w);
        }
        __syncthreads();

        if (t + 1 < ktiles) {
            int k0 = (t + 1) << 5;
            #pragma unroll
            for (int i = 0; i < 4; i++) {
                int r = srow + i * 32;
                xv[i] = *(const float4*)&X[(size_t)(row0 + r) * K + k0 + sc4];
                wv[i] = *(const float4*)&W[(size_t)(col0 + r) * K + k0 + sc4];
            }
        }

        #pragma unroll
        for (int kk = 0; kk < 4; kk++) {
            int k0 = kk << 3;
            unsigned a[4][4], b[4][2];
            #pragma unroll
            for (int mi = 0; mi < 4; mi++) {
                int rb = wm + mi * 16;
                a[mi][0] = As[(rb + g)     * GS + k0 + tig];
                a[mi][1] = As[(rb + g + 8) * GS + k0 + tig];
                a[mi][2] = As[(rb + g)     * GS + k0 + tig + 4];
                a[mi][3] = As[(rb + g + 8) * GS + k0 + tig + 4];
            }
            #pragma unroll
            for (int ni = 0; ni < 4; ni++) {
                int cb = wn + ni * 8;
                b[ni][0] = Bs[(cb + g) * GS + k0 + tig];
                b[ni][1] = Bs[(cb + g) * GS + k0 + tig + 4];
            }
            #pragma unroll
            for (int mi = 0; mi < 4; mi++)
                #pragma unroll
                for (int ni = 0; ni < 4; ni++)
                    mma_tf32(acc[mi][ni][0], acc[mi][ni][1],
                             acc[mi][ni][2], acc[mi][ni][3],
                             a[mi][0], a[mi][1], a[mi][2], a[mi][3],
                             b[ni][0], b[ni][1]);
        }
        __syncthreads();
    }

    #pragma unroll
    for (int mi = 0; mi < 4; mi++) {
        #pragma unroll
        for (int half = 0; half < 2; half++) {
            int m = row0 + wm + mi * 16 + g + half * 8;
            #pragma unroll
            for (int ni = 0; ni < 4; ni++) {
                int n = col0 + wn + ni * 8 + tig * 2;
                float v0 = acc[mi][ni][half * 2 + 0];
                float v1 = acc[mi][ni][half * 2 + 1];
                if (bias) { v0 += bias[n]; v1 += bias[n + 1]; }
                if (mode == 0) {
                    out[(size_t)m * N + n]     = v0;
                    out[(size_t)m * N + n + 1] = v1;
                } else {
                    int b_  = m >> 11;
                    int s_  = m & 2047;
                    int h_  = n >> 6;
                    int d_  = n & 63;
                    size_t base = (((size_t)(b_ * NH + h_)) * SEQ + s_) * HD;
                    out[base + d_]     = v0;
                    out[base + d_ + 1] = v1;
                }
            }
        }
    }
}

// ---------------------------------------------------------------------------
// Tensor-core flash attention (tf32 mma).
// Block: 64 q-rows x one (b,h). 4 warps, 16 q-rows each.
// Q a-frags resident in registers (scaled). K/V via cp.async into smem.
// Softmax in fragment space (shfl reductions). P via warp-private smem strip
// with XOR-4 swizzle (conflict-free stores AND a-frag loads).
// ---------------------------------------------------------------------------
#define KST 68
#define VST 72
#define PST 72
#define FLASH_SMEM ((64*KST + 64*VST + 64*PST + 64) * 4)

__global__ void __launch_bounds__(128) flash_tc_kernel(
    const int* __restrict__ pmask,   // (B, SEQ) int32
    const int* __restrict__ fmask,   // scalar int32
    float* __restrict__ ctx)         // (B, SEQ, INNER)
{
    extern __shared__ float sm[];
    float* Ks      = sm;                    // 64*KST
    float* Vs      = Ks + 64 * KST;         // 64*VST
    float* Ps      = Vs + 64 * VST;         // 64*PST
    float* maskadd = Ps + 64 * PST;         // 64

    const int tid  = threadIdx.x;
    const int warp = tid >> 5;
    const int lane = tid & 31;
    const int g    = lane >> 2;
    const int tig  = lane & 3;
    const int swc  = g & 4;                 // XOR swizzle for Ps

    const int qt = gridDim.x - 1 - blockIdx.x;  // heavy tiles first
    const int bh = blockIdx.y;
    const int b  = bh >> 4;
    const int h  = bh & 15;
    const int fut = fmask[0];

    const float* Qg = g_q + (size_t)bh * SEQ * HD;
    const float* Kg = g_k + (size_t)bh * SEQ * HD;
    const float* Vg = g_v + (size_t)bh * SEQ * HD;

    // Q a-fragments, scale 1/sqrt(64)=0.125 folded in.
    const int r0 = qt * 64 + warp * 16;
    unsigned qa[8][4];
    #pragma unroll
    for (int kc = 0; kc < 8; kc++) {
        qa[kc][0] = f2tf32(0.125f * Qg[(size_t)(r0 + g)     * HD + kc * 8 + tig]);
        qa[kc][1] = f2tf32(0.125f * Qg[(size_t)(r0 + g + 8) * HD + kc * 8 + tig]);
        qa[kc][2] = f2tf32(0.125f * Qg[(size_t)(r0 + g)     * HD + kc * 8 + tig + 4]);
        qa[kc][3] = f2tf32(0.125f * Qg[(size_t)(r0 + g + 8) * HD + kc * 8 + tig + 4]);
    }

    float om0 = -1e30f, om1 = -1e30f;   // running max (rows g, g+8)
    float ol0 = 0.0f,   ol1 = 0.0f;     // running sum
    float oacc[8][4] = {};              // O c-frags: [d-block][c0..c3]

    const int rowg0 = r0 + g;
    const int rowg1 = r0 + g + 8;

    const int ktmax = fut ? qt : (SEQ / 64 - 1);
    for (int kt = 0; kt <= ktmax; kt++) {
        __syncthreads();   // prior-tile frag reads complete

        // K/V tile -> smem via cp.async (16B each, 8+8 per thread)
        #pragma unroll
        for (int i = 0; i < 8; i++) {
            int idx = tid + i * 128;       // 0..1023
            int r = idx >> 4;
            int c = (idx & 15) << 2;
            cp16(&Ks[r * KST + c], &Kg[(size_t)(kt * 64 + r) * HD + c]);
            cp16(&Vs[r * VST + c], &Vg[(size_t)(kt * 64 + r) * HD + c]);
        }
        if (tid < 64)
            maskadd[tid] = pmask[b * SEQ + kt * 64 + tid] ? 0.0f : -1e30f;
        asm volatile("cp.async.wait_all;" ::: "memory");
        __syncthreads();

        // ---- S = Q K^T  (8 col-blocks x 8 k-steps) ----
        float s[8][4];
        #pragma unroll
        for (int j = 0; j < 8; j++) { s[j][0]=0; s[j][1]=0; s[j][2]=0; s[j][3]=0; }
        #pragma unroll
        for (int j = 0; j < 8; j++) {
            #pragma unroll
            for (int ks = 0; ks < 8; ks++) {
                unsigned b0 = __float_as_uint(Ks[(8*j + g) * KST + 8*ks + tig]);
                unsigned b1 = __float_as_uint(Ks[(8*j + g) * KST + 8*ks + tig + 4]);
                mma_tf32(s[j][0], s[j][1], s[j][2], s[j][3],
                         qa[ks][0], qa[ks][1], qa[ks][2], qa[ks][3], b0, b1);
            }
        }

        // ---- masks ----
        const bool diag = fut && (kt == qt);
        #pragma unroll
        for (int j = 0; j < 8; j++) {
            int c0 = 8*j + 2*tig;
            float ma0 = maskadd[c0];
            float ma1 = maskadd[c0 + 1];
            s[j][0] += ma0; s[j][1] += ma1;
            s[j][2] += ma0; s[j][3] += ma1;
            if (diag) {
                int gc0 = kt * 64 + c0;
                if (gc0     > rowg0) s[j][0] = -1e30f;
                if (gc0 + 1 > rowg0) s[j][1] = -1e30f;
                if (gc0     > rowg1) s[j][2] = -1e30f;
                if (gc0 + 1 > rowg1) s[j][3] = -1e30f;
            }
        }

        // ---- online softmax (frag space; reduce over tig via shfl) ----
        float mx0 = -1e30f, mx1 = -1e30f;
        #pragma unroll
        for (int j = 0; j < 8; j++) {
            mx0 = fmaxf(mx0, fmaxf(s[j][0], s[j][1]));
            mx1 = fmaxf(mx1, fmaxf(s[j][2], s[j][3]));
        }
        mx0 = fmaxf(mx0, __shfl_xor_sync(0xffffffffu, mx0, 1));
        mx0 = fmaxf(mx0, __shfl_xor_sync(0xffffffffu, mx0, 2));
        mx1 = fmaxf(mx1, __shfl_xor_sync(0xffffffffu, mx1, 1));
        mx1 = fmaxf(mx1, __shfl_xor_sync(0xffffffffu, mx1, 2));

        float mn0 = fmaxf(om0, mx0);
        float mn1 = fmaxf(om1, mx1);
        float cf0 = __expf(om0 - mn0);
        float cf1 = __expf(om1 - mn1);
        om0 = mn0; om1 = mn1;

        __syncwarp();   // prior-tile Ps a-frag reads complete (warp-private)

        float sum0 = 0.0f, sum1 = 0.0f;
        #pragma unroll
        for (int j = 0; j < 8; j++) {
            float p0 = __expf(s[j][0] - mn0);
            float p1 = __expf(s[j][1] - mn0);
            float p2 = __expf(s[j][2] - mn1);
            float p3 = __expf(s[j][3] - mn1);
            sum0 += p0 + p1;
            sum1 += p2 + p3;
            int cs = 8*j + ((2*tig) ^ swc);      // swizzled col
            float2 lo = make_float2(__uint_as_float(f2tf32(p0)),
                                    __uint_as_float(f2tf32(p1)));
            float2 hi = make_float2(__uint_as_float(f2tf32(p2)),
                                    __uint_as_float(f2tf32(p3)));
            *(float2*)&Ps[(warp*16 + g)     * PST + cs] = lo;
            *(float2*)&Ps[(warp*16 + g + 8) * PST + cs] = hi;
        }
        sum0 += __shfl_xor_sync(0xffffffffu, sum0, 1);
        sum0 += __shfl_xor_sync(0xffffffffu, sum0, 2);
        sum1 += __shfl_xor_sync(0xffffffffu, sum1, 1);
        sum1 += __shfl_xor_sync(0xffffffffu, sum1, 2);
        ol0 = ol0 * cf0 + sum0;
        ol1 = ol1 * cf1 + sum1;

        // rescale O accumulators
        #pragma unroll
        for (int j = 0; j < 8; j++) {
            oacc[j][0] *= cf0; oacc[j][1] *= cf0;
            oacc[j][2] *= cf1; oacc[j][3] *= cf1;
        }
        __syncwarp();   // P strip visible to whole warp

        // ---- load P a-frags (swizzled, conflict-free) ----
        unsigned pa[8][4];
        #pragma unroll
        for (int kc = 0; kc < 8; kc++) {
            int cA = 8*kc + (tig ^ swc);
            int cB = 8*kc + ((tig + 4) ^ swc);
            pa[kc][0] = __float_as_uint(Ps[(warp*16 + g)     * PST + cA]);
            pa[kc][1] = __float_as_uint(Ps[(warp*16 + g + 8) * PST + cA]);
            pa[kc][2] = __float_as_uint(Ps[(warp*16 + g)     * PST + cB]);
            pa[kc][3] = __float_as_uint(Ps[(warp*16 + g + 8) * PST + cB]);
        }

        // ---- O += P V  (8 d-blocks x 8 k-steps) ----
        #pragma unroll
        for (int j = 0; j < 8; j++) {
            #pragma unroll
            for (int ks = 0; ks < 8; ks++) {
                unsigned b0 = __float_as_uint(Vs[(8*ks + tig)     * VST + 8*j + g]);
                unsigned b1 = __float_as_uint(Vs[(8*ks + tig + 4) * VST + 8*j + g]);
                mma_tf32(oacc[j][0], oacc[j][1], oacc[j][2], oacc[j][3],
                         pa[ks][0], pa[ks][1], pa[ks][2], pa[ks][3], b0, b1);
            }
        }
    }

    // ---- epilogue: normalize + store ----
    float inv0 = (ol0 > 0.0f) ? (1.0f / ol0) : 0.0f;
    float inv1 = (ol1 > 0.0f) ? (1.0f / ol1) : 0.0f;
    #pragma unroll
    for (int j = 0; j < 8; j++) {
        int n = h * HD + 8*j + 2*tig;
        size_t base0 = ((size_t)b * SEQ + rowg0) * INNER + n;
        size_t base1 = ((size_t)b * SEQ + rowg1) * INNER + n;
        *(float2*)&ctx[base0] = make_float2(oacc[j][0] * inv0, oacc[j][1] * inv0);
        *(float2*)&ctx[base1] = make_float2(oacc[j][2] * inv1, oacc[j][3] * inv1);
    }
}

// ---------------------------------------------------------------------------
// Launch
// ---------------------------------------------------------------------------
extern "C" void kernel_launch(void* const* d_in, const int* in_sizes, int n_in,
                              void* d_out, int out_size)
{
    const float* q  = (const float*)d_in[0];
    const float* k  = (const float*)d_in[1];
    const float* v  = (const float*)d_in[2];
    const int*   pm = (const int*)d_in[3];
    const int*   fm = (const int*)d_in[4];
    const float* Wq = (const float*)d_in[5];
    const float* Wk = (const float*)d_in[6];
    const float* Wv = (const float*)d_in[7];
    const float* Wo = (const float*)d_in[8];
    const float* bo = (const float*)d_in[9];
    float* out = (float*)d_out;

    float *gq, *gk, *gv, *gctx;
    cudaGetSymbolAddress((void**)&gq,   g_q);
    cudaGetSymbolAddress((void**)&gk,   g_k);
    cudaGetSymbolAddress((void**)&gv,   g_v);
    cudaGetSymbolAddress((void**)&gctx, g_ctx);

    dim3 gblk(256);
    dim3 ggrd(INNER / 128, MTOT / 128);  // (8, 32)

    // QKV projections -> (B,H,S,D) layout (tf32 tensor cores)
    gemm_tc_kernel<<<ggrd, gblk>>>(q, Wq, gq, nullptr, MTOT, INNER, EMB, 1);
    gemm_tc_kernel<<<ggrd, gblk>>>(k, Wk, gk, nullptr, MTOT, INNER, EMB, 1);
    gemm_tc_kernel<<<ggrd, gblk>>>(v, Wv, gv, nullptr, MTOT, INNER, EMB, 1);

    // Flash attention (tf32 tensor cores)
    cudaFuncSetAttribute(flash_tc_kernel,
                         cudaFuncAttributeMaxDynamicSharedMemorySize, FLASH_SMEM);
    flash_tc_kernel<<<dim3(SEQ / 64, BATCH * NH), 128, FLASH_SMEM>>>(pm, fm, gctx);

    // Output projection + bias (tf32 tensor cores)
    gemm_tc_kernel<<<ggrd, gblk>>>(gctx, Wo, out, bo, MTOT, EMB, INNER, 0);
}